// round 15
// baseline (speedup 1.0000x reference)
#include <cuda_runtime.h>
#include <cuda_bf16.h>
#include <cstdint>

#define PP   64
#define HH   256
#define BB   32
#define TT   128
#define LE   10
#define LSTEPS 118
#define K3H  768
#define NCH  20
#define RING 4
#define CHUNK_BYTES 24576

#define PRED_ELEMS (PP * BB * LSTEPS)
#define MU_OFF     PRED_ELEMS
#define LV_OFF     (PRED_ELEMS + BB * HH)

// ---- dec smem offsets ------------------------------------------------------
#define FULL_OFF   0        // 4 x 8B
#define EMPTY_OFF  32       // 4 x 8B
#define STEP_OFF   64       // 8B, count 32 (16 local + 16 remote lane0s)
#define PART_OFF   128      // 2 buf x 32 floats
#define RED_OFF    384      // 16 x 16 floats = 1024B
#define V_OFF      1536     // 2 x VBUF
#define VBUF       51200    // hi 25600 + lo 25600 (160 rows x 40 words x 4B)
#define VLO        25600
#define RING_OFF   104448   // 4 x 24576
#define SMEM_TOTAL 202752
#define ENC_SMEM   200448

__device__ __align__(16) unsigned char g_Wpk[(size_t)PP * 2 * NCH * CHUNK_BYTES];
__device__ uint32_t g_Xpk[LSTEPS * 2 * 1024];   // [l][hi/lo][k2(32)*32 + b]
__device__ float g_xpe[LE * BB * K3H];
__device__ float g_hT[BB * HH];
__device__ float g_z[BB * HH];

typedef unsigned long long ull;
__device__ __forceinline__ uint32_t s2u(const void* p) {
    uint32_t a;
    asm("{ .reg .u64 t; cvta.to.shared.u64 t, %1; cvt.u32.u64 %0, t; }" : "=r"(a) : "l"(p));
    return a;
}
__device__ __forceinline__ float sigf(float x) { return __fdividef(1.0f, 1.0f + __expf(-x)); }
__device__ __forceinline__ float tfast(float x) {
    float e = __expf(2.0f * x);
    return 1.0f - __fdividef(2.0f, e + 1.0f);
}
__device__ __forceinline__ void mbar_init(uint32_t mb, uint32_t cnt) {
    asm volatile("mbarrier.init.shared.b64 [%0], %1;" :: "r"(mb), "r"(cnt) : "memory");
}
__device__ __forceinline__ void mbar_arrive(uint32_t mb) {
    asm volatile("mbarrier.arrive.shared.b64 _, [%0];" :: "r"(mb) : "memory");
}
__device__ __forceinline__ void mbar_arrive_cluster_rel(uint32_t mb) {
    asm volatile("mbarrier.arrive.release.cluster.shared::cluster.b64 _, [%0];"
                 :: "r"(mb) : "memory");
}
__device__ __forceinline__ void mbar_expect(uint32_t mb, uint32_t bytes) {
    asm volatile("mbarrier.arrive.expect_tx.shared.b64 _, [%0], %1;"
                 :: "r"(mb), "r"(bytes) : "memory");
}
__device__ __forceinline__ void mwait(uint32_t mb, uint32_t par) {
    asm volatile(
        "{\n\t.reg .pred P;\n"
        "LW%=:\n\t"
        "mbarrier.try_wait.parity.acquire.cta.shared::cta.b64 P, [%0], %1, 0x989680;\n\t"
        "@!P bra LW%=;\n\t}"
        :: "r"(mb), "r"(par) : "memory");
}
__device__ __forceinline__ void mwait_cl(uint32_t mb, uint32_t par) {
    asm volatile(
        "{\n\t.reg .pred P;\n"
        "LW%=:\n\t"
        "mbarrier.try_wait.parity.acquire.cluster.shared::cta.b64 P, [%0], %1, 0x989680;\n\t"
        "@!P bra LW%=;\n\t}"
        :: "r"(mb), "r"(par) : "memory");
}
__device__ __forceinline__ void bulk_cp(uint32_t dst, const void* src, uint32_t bytes,
                                        uint32_t mb) {
    asm volatile(
        "cp.async.bulk.shared::cluster.global.mbarrier::complete_tx::bytes [%0], [%1], %2, [%3];"
        :: "r"(dst), "l"(src), "r"(bytes), "r"(mb) : "memory");
}
__device__ __forceinline__ void lm4(uint32_t* r, uint32_t addr) {
    asm volatile("ldmatrix.sync.aligned.m8n8.x4.shared.b16 {%0,%1,%2,%3}, [%4];"
                 : "=r"(r[0]), "=r"(r[1]), "=r"(r[2]), "=r"(r[3]) : "r"(addr));
}
__device__ __forceinline__ void mma16816(float* c, const uint32_t* a,
                                         uint32_t b0, uint32_t b1) {
    asm volatile(
        "mma.sync.aligned.m16n8k16.row.col.f32.bf16.bf16.f32 "
        "{%0,%1,%2,%3}, {%4,%5,%6,%7}, {%8,%9}, {%0,%1,%2,%3};"
        : "+f"(c[0]), "+f"(c[1]), "+f"(c[2]), "+f"(c[3])
        : "r"(a[0]), "r"(a[1]), "r"(a[2]), "r"(a[3]), "r"(b0), "r"(b1));
}
__device__ __forceinline__ uint32_t packbf2(float v0, float v1) {
    __nv_bfloat16 h0 = __float2bfloat16(v0), h1 = __float2bfloat16(v1);
    uint16_t u0 = *(uint16_t*)&h0, u1 = *(uint16_t*)&h1;
    return (uint32_t)u0 | ((uint32_t)u1 << 16);
}
__device__ __forceinline__ uint16_t bfbits(float v) {
    __nv_bfloat16 h = __float2bfloat16(v);
    return *(uint16_t*)&h;
}
__device__ __forceinline__ uint32_t mapa_u32(uint32_t addr, uint32_t rank) {
    uint32_t r;
    asm("mapa.shared::cluster.u32 %0, %1, %2;" : "=r"(r) : "r"(addr), "r"(rank));
    return r;
}
__device__ __forceinline__ void st_cl_b16(uint32_t addr, uint16_t v) {
    asm volatile("st.shared::cluster.b16 [%0], %1;" :: "r"(addr), "h"(v) : "memory");
}
__device__ __forceinline__ void st_cl_f32(uint32_t addr, float v) {
    asm volatile("st.shared::cluster.f32 [%0], %1;" :: "r"(addr), "f"(v) : "memory");
}
#define CLUSTER_SYNC() do { \
    asm volatile("barrier.cluster.arrive.aligned;" ::: "memory"); \
    asm volatile("barrier.cluster.wait.aligned;" ::: "memory"); } while (0)

// ---- prepack weights: per (p, jhalf) chunk images [wc(8)][gate(3)][hl(2)]x512B
__global__ void packW_kernel(const float* __restrict__ Whh,
                             const float* __restrict__ Wih) {
    int bx = blockIdx.x, c = blockIdx.y;   // bx = p*2 + jhalf
    int p = bx >> 1, jhalf = bx & 1;
    unsigned char* img = g_Wpk + ((size_t)bx * NCH + c) * CHUNK_BYTES;
    for (int idx = threadIdx.x; idx < 6144; idx += 256) {
        int kk = idx & 15, t = idx >> 4;
        int r = t & 15, t2 = t >> 4;
        int g = t2 % 3, wc = t2 / 3;
        int j = jhalf * 128 + wc * 16 + r;
        int k = c * 16 + kk;
        float v = (c < 16)
            ? Whh[((size_t)p * K3H + g * 256 + j) * HH + k]
            : Wih[((size_t)p * K3H + g * 256 + j) * PP + (k - 256)];
        __nv_bfloat16 hi = __float2bfloat16(v);
        __nv_bfloat16 lo = __float2bfloat16(v - __bfloat162float(hi));
        uint32_t off = (uint32_t)(((wc * 3 + g) * 2) * 512 + r * 32 + kk * 2);
        *(__nv_bfloat16*)(img + off) = hi;
        *(__nv_bfloat16*)(img + off + 512) = lo;
    }
}

// ---- prepack x words: [l][t][k2*32 + b] --------------------------------------
__global__ void packX_kernel(const float* __restrict__ X) {
    int l = blockIdx.x;
    for (int e = threadIdx.x; e < 2048; e += 256) {
        int t = e >> 10, w = e & 1023;
        int k2 = w >> 5, b = w & 31;
        float v0 = 0.f, v1 = 0.f;
        if (l != 0) {
            v0 = X[(size_t)b * TT * PP + (l + 9) * PP + 2 * k2];
            v1 = X[(size_t)b * TT * PP + (l + 9) * PP + 2 * k2 + 1];
        }
        uint32_t word;
        if (t == 0) word = packbf2(v0, v1);
        else {
            float h0 = __bfloat162float(__float2bfloat16(v0));
            float h1 = __bfloat162float(__float2bfloat16(v1));
            word = packbf2(v0 - h0, v1 - h1);
        }
        g_Xpk[(l * 2 + t) * 1024 + w] = word;
    }
}

__global__ void xpe_kernel(const float* __restrict__ X,
                           const float* __restrict__ Wih_e,
                           const float* __restrict__ bih_e) {
    __shared__ float xr[PP];
    int b = blockIdx.x, l = blockIdx.y, tid = threadIdx.x;
    if (tid < PP) xr[tid] = X[b * (TT * PP) + l * PP + tid];
    __syncthreads();
#pragma unroll
    for (int g = 0; g < 3; ++g) {
        int k = g * HH + tid;
        float a = bih_e[k];
        const float* w = Wih_e + k * PP;
#pragma unroll
        for (int i = 0; i < PP; i += 4) {
            float4 wv = *(const float4*)(w + i);
            a += wv.x * xr[i] + wv.y * xr[i + 1] + wv.z * xr[i + 2] + wv.w * xr[i + 3];
        }
        g_xpe[(l * BB + b) * K3H + k] = a;
    }
}

// ---- encoder GRU: cluster(4) per batch element, smem-resident weights --------
extern __shared__ float esm[];
__global__ void __launch_bounds__(256, 1) __cluster_dims__(4, 1, 1)
enc_kernel(const float* __restrict__ Whh_e, const float* __restrict__ bhh_e) {
    float* wst = esm;                // [256][193]
    float* hb  = esm + 49408;       // [2][256]
    float* ap  = esm + 49920;       // [192]
    const int tid = threadIdx.x;
    const int b = blockIdx.x >> 2;
    uint32_t rank;
    asm("mov.u32 %0, %%cluster_ctarank;" : "=r"(rank));

    for (int e = tid; e < 192 * 256; e += 256) {
        int row = e >> 8, k = e & 255;
        int g = row >> 6, jj = row & 63;
        wst[k * 193 + row] = Whh_e[(size_t)(g * 256 + rank * 64 + jj) * 256 + k];
    }
    hb[tid] = 0.f;
    hb[256 + tid] = 0.f;
    float bh = 0.f;
    if (tid < 192) {
        int g = tid >> 6, jj = tid & 63;
        bh = bhh_e[g * 256 + rank * 64 + jj];
    }
    __syncthreads();
    CLUSTER_SYNC();

    for (int l = 0; l < LE; ++l) {
        const float* hc = hb + (l & 1) * 256;
        if (tid < 192) {
            float a0 = 0.f, a1 = 0.f, a2 = 0.f, a3 = 0.f;
#pragma unroll 8
            for (int k = 0; k < 256; k += 4) {
                float4 hv = *(const float4*)&hc[k];
                a0 += wst[k * 193 + tid] * hv.x;
                a1 += wst[(k + 1) * 193 + tid] * hv.y;
                a2 += wst[(k + 2) * 193 + tid] * hv.z;
                a3 += wst[(k + 3) * 193 + tid] * hv.w;
            }
            ap[tid] = a0 + a1 + a2 + a3 + bh;
        }
        __syncthreads();
        if (tid < 64) {
            int j = rank * 64 + tid;
            const float* xp = g_xpe + (l * BB + b) * K3H;
            float r = sigf(xp[j] + ap[tid]);
            float z = sigf(xp[HH + j] + ap[64 + tid]);
            float n = tfast(xp[2 * HH + j] + r * ap[128 + tid]);
            float hn = n + z * (hc[j] - n);
            float* dst = hb + ((l + 1) & 1) * 256 + j;
            *dst = hn;
            uint32_t la = s2u(dst);
#pragma unroll
            for (int pr = 0; pr < 4; ++pr)
                if (pr != (int)rank) st_cl_f32(mapa_u32(la, (uint32_t)pr), hn);
        }
        CLUSTER_SYNC();
    }
    if (rank == 0) g_hT[b * HH + tid] = hb[(LE & 1) * 256 + tid];
}

__global__ void muz_kernel(const float* __restrict__ Wmu, const float* __restrict__ bmu,
                           const float* __restrict__ Wstd, const float* __restrict__ bstd,
                           const float* __restrict__ eps, float* __restrict__ out) {
    __shared__ float hs[HH];
    int b = blockIdx.x, j = threadIdx.x;
    hs[j] = g_hT[b * HH + j];
    __syncthreads();
    float am = bmu[j], as = bstd[j];
    const float* wm = Wmu + j * HH;
    const float* ws = Wstd + j * HH;
#pragma unroll 8
    for (int h = 0; h < HH; h += 4) {
        float4 hv = *(const float4*)&hs[h];
        float4 m4 = *(const float4*)(wm + h);
        float4 s4 = *(const float4*)(ws + h);
        am += m4.x * hv.x + m4.y * hv.y + m4.z * hv.z + m4.w * hv.w;
        as += s4.x * hv.x + s4.y * hv.y + s4.z * hv.z + s4.w * hv.w;
    }
    out[MU_OFF + b * HH + j] = am;
    out[LV_OFF + b * HH + j] = as;
    g_z[b * HH + j] = am + expf(0.5f * as) * eps[b * HH + j];
}

// ---- decoder: cluster(2) j-split, 16 consumer warps (half-N each) ------------
extern __shared__ unsigned char smem[];

__global__ void __launch_bounds__(544, 1) __cluster_dims__(2, 1, 1) dec_kernel(
    const float* __restrict__ bih_d, const float* __restrict__ bhh_d,
    const float* __restrict__ Wlin, const float* __restrict__ blin,
    float* __restrict__ out) {
    const int tid = threadIdx.x;
    const int p = blockIdx.x >> 1, jhalf = blockIdx.x & 1;
    const int w = tid >> 5, lane = tid & 31;
    const int wc = w - 1;               // consumer warp 0..15
    const int wcm = wc >> 1;            // m-tile 0..7
    const int wcn = wc & 1;             // n-half 0..1
    const int g = lane >> 2, tig = lane & 3;
    const int ct = tid - 32;            // consumer thread 0..511
    const uint32_t sb = s2u(smem);
    const uint32_t peer_sb = mapa_u32(sb, (uint32_t)(jhalf ^ 1));

    if (tid == 0) {
#pragma unroll
        for (int s = 0; s < RING; ++s) {
            mbar_init(sb + FULL_OFF + s * 8, 1);
            mbar_init(sb + EMPTY_OFF + s * 8, 16);
        }
        mbar_init(sb + STEP_OFF, 32);
        asm volatile("fence.proxy.async.shared::cta;" ::: "memory");
    }

    const int jbase = jhalf * 128 + (wc >= 0 ? wcm * 16 : 0);
    float bR[2], bZ[2], bNx[2], bNh[2], wl[2];
    float hreg[8];
    if (wc >= 0) {
#pragma unroll
        for (int rr = 0; rr < 2; ++rr) {
            int j = jbase + g + rr * 8;
            bR[rr]  = bih_d[p * K3H + j] + bhh_d[p * K3H + j];
            bZ[rr]  = bih_d[p * K3H + 256 + j] + bhh_d[p * K3H + 256 + j];
            bNx[rr] = bih_d[p * K3H + 512 + j];
            bNh[rr] = bhh_d[p * K3H + 512 + j];
            wl[rr]  = Wlin[p * HH + j];
        }
#pragma unroll
        for (int ntl = 0; ntl < 2; ++ntl)
#pragma unroll
            for (int q = 0; q < 4; ++q) {
                int j = jbase + g + (q >> 1) * 8;
                int bcol = (wcn * 2 + ntl) * 8 + 2 * tig + (q & 1);
                hreg[ntl * 4 + q] = g_z[bcol * HH + j];
            }
        // v[0] h-region: consumer threads 0..255 cover all 256 j, 32 b
        if (ct < 256) {
            int j = ct;
            for (int b = 0; b < BB; ++b) {
                float v = g_z[b * HH + j];
                uint16_t hu = bfbits(v);
                uint16_t lu = bfbits(v - __bfloat162float(__float2bfloat16(v)));
                uint32_t ad = V_OFF + ((uint32_t)(j >> 1) * 40 + b) * 4 + (j & 1) * 2;
                *(uint16_t*)(smem + ad) = hu;
                *(uint16_t*)(smem + ad + VLO) = lu;
            }
        }
        // v[0] x-region: 1024 words over 512 consumers (2 each)
        for (int q = 0; q < 2; ++q) {
            int wd = ct * 2 + q;
            int k2 = wd >> 5, col = wd & 31;
            uint32_t ad = V_OFF + ((uint32_t)(128 + k2) * 40 + col) * 4;
            *(uint32_t*)(smem + ad) = g_Xpk[wd];
            *(uint32_t*)(smem + ad + VLO) = g_Xpk[1024 + wd];
        }
    }
    const float blin_p = blin[p];
    __syncthreads();
    CLUSTER_SYNC();

    const uint32_t laneoff = (uint32_t)((((lane >> 3) & 1) * 8 + (lane & 7)) * 32 +
                                        ((lane >> 4) & 1) * 16);
    const unsigned char* wsrc = g_Wpk + (size_t)blockIdx.x * NCH * CHUNK_BYTES;
    float* red = (float*)(smem + RED_OFF);

    for (int l = 0; l < LSTEPS; ++l) {
        if (w == 0) {
            if (lane == 0) {
                for (int c = 0; c < NCH; ++c) {
                    int n = l * NCH + c, s = n & 3;
                    mwait(sb + EMPTY_OFF + s * 8, (uint32_t)(((n >> 2) + 1) & 1));
                    mbar_expect(sb + FULL_OFF + s * 8, CHUNK_BYTES);
                    bulk_cp(sb + RING_OFF + s * CHUNK_BYTES,
                            wsrc + (size_t)c * CHUNK_BYTES, CHUNK_BYTES,
                            sb + FULL_OFF + s * 8);
                }
            }
            __syncthreads();
        } else {
            const uint32_t vc = V_OFF + (uint32_t)(l & 1) * VBUF;
            const uint32_t vn = V_OFF + (uint32_t)((l + 1) & 1) * VBUF;
            float accR[2][4], accZ[2][4], accNh[2][4], accNx[2][4];
#pragma unroll
            for (int ntl = 0; ntl < 2; ++ntl)
#pragma unroll
                for (int q = 0; q < 4; ++q) {
                    accR[ntl][q] = 0.f; accZ[ntl][q] = 0.f;
                    accNh[ntl][q] = 0.f; accNx[ntl][q] = 0.f;
                }

#pragma unroll 1
            for (int c = 0; c < NCH; ++c) {
                int n = l * NCH + c, s = n & 3;
                mwait(sb + FULL_OFF + s * 8, (uint32_t)((n >> 2) & 1));

                uint32_t bh[2][2], bl[2][2];
#pragma unroll
                for (int hf = 0; hf < 2; ++hf)
#pragma unroll
                    for (int ntl = 0; ntl < 2; ++ntl) {
                        int nt = wcn * 2 + ntl;
                        uint32_t wo = vc + ((uint32_t)(8 * c + hf * 4 + tig) * 40 +
                                            nt * 8 + g) * 4;
                        bh[hf][ntl] = *(const uint32_t*)(smem + wo);
                        bl[hf][ntl] = *(const uint32_t*)(smem + wo + VLO);
                    }

                uint32_t tb = sb + RING_OFF + s * CHUNK_BYTES + wcm * 3072 + laneoff;
#pragma unroll
                for (int gate = 0; gate < 3; ++gate) {
                    uint32_t ahi[4], alo[4];
                    lm4(ahi, tb + gate * 1024);
                    lm4(alo, tb + gate * 1024 + 512);
                    float (*acc)[4] =
                        (gate == 0) ? accR :
                        (gate == 1) ? accZ :
                        (c < 16 ? accNh : accNx);
#pragma unroll
                    for (int ntl = 0; ntl < 2; ++ntl) {
                        mma16816(acc[ntl], ahi, bh[0][ntl], bh[1][ntl]);
                        mma16816(acc[ntl], ahi, bl[0][ntl], bl[1][ntl]);
                        mma16816(acc[ntl], alo, bh[0][ntl], bh[1][ntl]);
                    }
                }
                if (lane == 0) mbar_arrive(sb + EMPTY_OFF + s * 8);
            }

            // -------- epilogue: gates, h update, v[nxt] local + peer --------
            float part[4];
#pragma unroll
            for (int q = 0; q < 4; ++q) part[q] = 0.f;
#pragma unroll
            for (int ntl = 0; ntl < 2; ++ntl)
#pragma unroll
                for (int q = 0; q < 4; ++q) {
                    int rr = q >> 1, cc = q & 1;
                    float r = sigf(accR[ntl][q] + bR[rr]);
                    float z = sigf(accZ[ntl][q] + bZ[rr]);
                    float nn = tfast(accNx[ntl][q] + bNx[rr] +
                                     r * (accNh[ntl][q] + bNh[rr]));
                    float hn = nn + z * (hreg[ntl * 4 + q] - nn);
                    hreg[ntl * 4 + q] = hn;
                    int j = jbase + g + rr * 8;
                    int bcol = (wcn * 2 + ntl) * 8 + 2 * tig + cc;
                    uint16_t hu = bfbits(hn);
                    uint16_t lu = bfbits(hn - __bfloat162float(__float2bfloat16(hn)));
                    uint32_t ad = vn + ((uint32_t)(j >> 1) * 40 + bcol) * 4 + (j & 1) * 2;
                    *(uint16_t*)(smem + ad) = hu;
                    *(uint16_t*)(smem + ad + VLO) = lu;
                    st_cl_b16(peer_sb + ad, hu);
                    st_cl_b16(peer_sb + ad + VLO, lu);
                    part[ntl * 2 + cc] += hn * wl[rr];
                }
            // x region for step l+1 (local only)
            if (l + 1 < LSTEPS) {
                const uint32_t* src = g_Xpk + (size_t)(l + 1) * 2048;
#pragma unroll
                for (int q = 0; q < 2; ++q) {
                    int wd = ct * 2 + q;
                    int k2 = wd >> 5, col = wd & 31;
                    uint32_t ad = vn + ((uint32_t)(128 + k2) * 40 + col) * 4;
                    *(uint32_t*)(smem + ad) = src[wd];
                    *(uint32_t*)(smem + ad + VLO) = src[1024 + wd];
                }
            }
            // reduce Wlin partials over g (shfl offsets 16, 8, 4)
#pragma unroll
            for (int off = 16; off >= 4; off >>= 1)
#pragma unroll
                for (int q = 0; q < 4; ++q)
                    part[q] += __shfl_down_sync(0xffffffffu, part[q], off);
            if (lane < 4) {
#pragma unroll
                for (int ntl = 0; ntl < 2; ++ntl)
#pragma unroll
                    for (int cc = 0; cc < 2; ++cc)
                        red[wc * 16 + ntl * 8 + 2 * lane + cc] = part[ntl * 2 + cc];
            }
            __syncthreads();   // all local v/red writes CTA-visible

            float s0 = 0.f;
            if (w == 1) {      // lane = global b (0..31)
                int row = lane >> 4;       // wcn selector
                int idx = lane & 15;
#pragma unroll
                for (int m = 0; m < 8; ++m) s0 += red[(m * 2 + row) * 16 + idx];
                st_cl_f32(peer_sb + PART_OFF + (uint32_t)(l & 1) * 128 + lane * 4, s0);
            }
            __syncwarp();      // PART stores HB lane0's release
            if (lane == 0) {
                mbar_arrive(sb + STEP_OFF);
                mbar_arrive_cluster_rel(peer_sb + STEP_OFF);
            }
            mwait_cl(sb + STEP_OFF, (uint32_t)(l & 1));
            if (w == 1 && jhalf == 0) {
                float ph = *(const float*)(smem + PART_OFF + (uint32_t)(l & 1) * 128 +
                                           lane * 4);
                out[(p * BB + lane) * LSTEPS + l] = s0 + ph + blin_p;
            }
        }
    }
    CLUSTER_SYNC();
}

// -----------------------------------------------------------------------------
extern "C" void kernel_launch(void* const* d_in, const int* in_sizes, int n_in,
                              void* d_out, int out_size) {
    const float* X     = (const float*)d_in[0];
    const float* eps   = (const float*)d_in[1];
    const float* Wih_e = (const float*)d_in[3];
    const float* Whh_e = (const float*)d_in[4];
    const float* bih_e = (const float*)d_in[5];
    const float* bhh_e = (const float*)d_in[6];
    const float* Wmu   = (const float*)d_in[7];
    const float* bmu   = (const float*)d_in[8];
    const float* Wstd  = (const float*)d_in[9];
    const float* bstd  = (const float*)d_in[10];
    const float* Wih_d = (const float*)d_in[11];
    const float* Whh_d = (const float*)d_in[12];
    const float* bih_d = (const float*)d_in[13];
    const float* bhh_d = (const float*)d_in[14];
    const float* Wlin  = (const float*)d_in[15];
    const float* blin  = (const float*)d_in[16];
    float* out = (float*)d_out;

    static int attr_set = 0;
    if (!attr_set) {
        cudaFuncSetAttribute(dec_kernel, cudaFuncAttributeMaxDynamicSharedMemorySize,
                             SMEM_TOTAL);
        cudaFuncSetAttribute(enc_kernel, cudaFuncAttributeMaxDynamicSharedMemorySize,
                             ENC_SMEM);
        attr_set = 1;
    }

    packW_kernel<<<dim3(PP * 2, NCH), 256>>>(Whh_d, Wih_d);
    packX_kernel<<<LSTEPS, 256>>>(X);
    xpe_kernel<<<dim3(BB, LE), 256>>>(X, Wih_e, bih_e);
    enc_kernel<<<BB * 4, 256, ENC_SMEM>>>(Whh_e, bhh_e);
    muz_kernel<<<BB, 256>>>(Wmu, bmu, Wstd, bstd, eps, out);
    dec_kernel<<<2 * PP, 544, SMEM_TOTAL>>>(bih_d, bhh_d, Wlin, blin, out);
}

// round 16
// speedup vs baseline: 1.4650x; 1.4650x over previous
#include <cuda_runtime.h>
#include <cuda_fp16.h>
#include <cstdint>

#define PP   64
#define HH   256
#define BB   32
#define TT   128
#define LE   10
#define LSTEPS 118
#define K3H  768
#define NCH  20
#define RING 4
#define CHUNK_BYTES 24576

#define PRED_ELEMS (PP * BB * LSTEPS)
#define MU_OFF     PRED_ELEMS
#define LV_OFF     (PRED_ELEMS + BB * HH)

// ---- dec smem offsets ------------------------------------------------------
#define FULL_OFF   0        // 4 x 8B
#define EMPTY_OFF  32       // 4 x 8B
#define STEP_OFF   64       // 8B, count 16 (8 local + 8 remote lane0s)
#define PART_OFF   128      // 2 buf x 32 floats
#define RED_OFF    384      // 8 x 32 floats
#define V_OFF      1536     // 2 x VBUF (single fp16 plane now)
#define VBUF       25600    // 160 rows x 40 words x 4B
#define RING_OFF   52736    // 1536 + 2*25600
#define SMEM_TOTAL 151040   // RING_OFF + 4*24576
#define ENC_SMEM   200448

__device__ __align__(16) unsigned char g_Wpk[(size_t)PP * 2 * NCH * CHUNK_BYTES];
__device__ uint32_t g_Xpk[LSTEPS * 1024];   // [l][k2(32)*32 + b], fp16x2 words
__device__ float g_xpe[LE * BB * K3H];
__device__ float g_hT[BB * HH];
__device__ float g_z[BB * HH];

typedef unsigned long long ull;
__device__ __forceinline__ uint32_t s2u(const void* p) {
    uint32_t a;
    asm("{ .reg .u64 t; cvta.to.shared.u64 t, %1; cvt.u32.u64 %0, t; }" : "=r"(a) : "l"(p));
    return a;
}
__device__ __forceinline__ float sigf(float x) { return __fdividef(1.0f, 1.0f + __expf(-x)); }
__device__ __forceinline__ float tfast(float x) {
    float e = __expf(2.0f * x);
    return 1.0f - __fdividef(2.0f, e + 1.0f);
}
__device__ __forceinline__ void mbar_init(uint32_t mb, uint32_t cnt) {
    asm volatile("mbarrier.init.shared.b64 [%0], %1;" :: "r"(mb), "r"(cnt) : "memory");
}
__device__ __forceinline__ void mbar_arrive(uint32_t mb) {
    asm volatile("mbarrier.arrive.shared.b64 _, [%0];" :: "r"(mb) : "memory");
}
__device__ __forceinline__ void mbar_arrive_cluster_rel(uint32_t mb) {
    asm volatile("mbarrier.arrive.release.cluster.shared::cluster.b64 _, [%0];"
                 :: "r"(mb) : "memory");
}
__device__ __forceinline__ void mbar_expect(uint32_t mb, uint32_t bytes) {
    asm volatile("mbarrier.arrive.expect_tx.shared.b64 _, [%0], %1;"
                 :: "r"(mb), "r"(bytes) : "memory");
}
__device__ __forceinline__ void mwait(uint32_t mb, uint32_t par) {
    asm volatile(
        "{\n\t.reg .pred P;\n"
        "LW%=:\n\t"
        "mbarrier.try_wait.parity.acquire.cta.shared::cta.b64 P, [%0], %1, 0x989680;\n\t"
        "@!P bra LW%=;\n\t}"
        :: "r"(mb), "r"(par) : "memory");
}
__device__ __forceinline__ void mwait_cl(uint32_t mb, uint32_t par) {
    asm volatile(
        "{\n\t.reg .pred P;\n"
        "LW%=:\n\t"
        "mbarrier.try_wait.parity.acquire.cluster.shared::cta.b64 P, [%0], %1, 0x989680;\n\t"
        "@!P bra LW%=;\n\t}"
        :: "r"(mb), "r"(par) : "memory");
}
__device__ __forceinline__ void bulk_cp(uint32_t dst, const void* src, uint32_t bytes,
                                        uint32_t mb) {
    asm volatile(
        "cp.async.bulk.shared::cluster.global.mbarrier::complete_tx::bytes [%0], [%1], %2, [%3];"
        :: "r"(dst), "l"(src), "r"(bytes), "r"(mb) : "memory");
}
__device__ __forceinline__ void lm4(uint32_t* r, uint32_t addr) {
    asm volatile("ldmatrix.sync.aligned.m8n8.x4.shared.b16 {%0,%1,%2,%3}, [%4];"
                 : "=r"(r[0]), "=r"(r[1]), "=r"(r[2]), "=r"(r[3]) : "r"(addr));
}
__device__ __forceinline__ void mma16816h(float* c, const uint32_t* a,
                                          uint32_t b0, uint32_t b1) {
    asm volatile(
        "mma.sync.aligned.m16n8k16.row.col.f32.f16.f16.f32 "
        "{%0,%1,%2,%3}, {%4,%5,%6,%7}, {%8,%9}, {%0,%1,%2,%3};"
        : "+f"(c[0]), "+f"(c[1]), "+f"(c[2]), "+f"(c[3])
        : "r"(a[0]), "r"(a[1]), "r"(a[2]), "r"(a[3]), "r"(b0), "r"(b1));
}
__device__ __forceinline__ uint32_t packh2(float v0, float v1) {
    __half h0 = __float2half(v0), h1 = __float2half(v1);
    uint16_t u0 = *(uint16_t*)&h0, u1 = *(uint16_t*)&h1;
    return (uint32_t)u0 | ((uint32_t)u1 << 16);
}
__device__ __forceinline__ uint16_t hbits(float v) {
    __half h = __float2half(v);
    return *(uint16_t*)&h;
}
__device__ __forceinline__ uint32_t mapa_u32(uint32_t addr, uint32_t rank) {
    uint32_t r;
    asm("mapa.shared::cluster.u32 %0, %1, %2;" : "=r"(r) : "r"(addr), "r"(rank));
    return r;
}
__device__ __forceinline__ void st_cl_b16(uint32_t addr, uint16_t v) {
    asm volatile("st.shared::cluster.b16 [%0], %1;" :: "r"(addr), "h"(v) : "memory");
}
__device__ __forceinline__ void st_cl_f32(uint32_t addr, float v) {
    asm volatile("st.shared::cluster.f32 [%0], %1;" :: "r"(addr), "f"(v) : "memory");
}
#define CLUSTER_SYNC() do { \
    asm volatile("barrier.cluster.arrive.aligned;" ::: "memory"); \
    asm volatile("barrier.cluster.wait.aligned;" ::: "memory"); } while (0)

// ---- prepack weights: fp16 hi/lo split, [wc(8)][gate(3)][hl(2)]x512B tiles ----
__global__ void packW_kernel(const float* __restrict__ Whh,
                             const float* __restrict__ Wih) {
    int bx = blockIdx.x, c = blockIdx.y;   // bx = p*2 + jhalf
    int p = bx >> 1, jhalf = bx & 1;
    unsigned char* img = g_Wpk + ((size_t)bx * NCH + c) * CHUNK_BYTES;
    for (int idx = threadIdx.x; idx < 6144; idx += 256) {
        int kk = idx & 15, t = idx >> 4;
        int r = t & 15, t2 = t >> 4;
        int g = t2 % 3, wc = t2 / 3;
        int j = jhalf * 128 + wc * 16 + r;
        int k = c * 16 + kk;
        float v = (c < 16)
            ? Whh[((size_t)p * K3H + g * 256 + j) * HH + k]
            : Wih[((size_t)p * K3H + g * 256 + j) * PP + (k - 256)];
        __half hi = __float2half(v);
        __half lo = __float2half(v - __half2float(hi));
        uint32_t off = (uint32_t)(((wc * 3 + g) * 2) * 512 + r * 32 + kk * 2);
        *(__half*)(img + off) = hi;
        *(__half*)(img + off + 512) = lo;
    }
}

// ---- prepack x words: [l][k2*32 + b], fp16 pair {x[2k2], x[2k2+1]} ------------
__global__ void packX_kernel(const float* __restrict__ X) {
    int l = blockIdx.x;
    for (int e = threadIdx.x; e < 1024; e += 256) {
        int k2 = e >> 5, b = e & 31;
        float v0 = 0.f, v1 = 0.f;
        if (l != 0) {
            v0 = X[(size_t)b * TT * PP + (l + 9) * PP + 2 * k2];
            v1 = X[(size_t)b * TT * PP + (l + 9) * PP + 2 * k2 + 1];
        }
        g_Xpk[l * 1024 + e] = packh2(v0, v1);
    }
}

__global__ void xpe_kernel(const float* __restrict__ X,
                           const float* __restrict__ Wih_e,
                           const float* __restrict__ bih_e) {
    __shared__ float xr[PP];
    int b = blockIdx.x, l = blockIdx.y, tid = threadIdx.x;
    if (tid < PP) xr[tid] = X[b * (TT * PP) + l * PP + tid];
    __syncthreads();
#pragma unroll
    for (int g = 0; g < 3; ++g) {
        int k = g * HH + tid;
        float a = bih_e[k];
        const float* w = Wih_e + k * PP;
#pragma unroll
        for (int i = 0; i < PP; i += 4) {
            float4 wv = *(const float4*)(w + i);
            a += wv.x * xr[i] + wv.y * xr[i + 1] + wv.z * xr[i + 2] + wv.w * xr[i + 3];
        }
        g_xpe[(l * BB + b) * K3H + k] = a;
    }
}

// ---- encoder GRU: cluster(4) per batch element, smem-resident weights --------
extern __shared__ float esm[];
__global__ void __launch_bounds__(256, 1) __cluster_dims__(4, 1, 1)
enc_kernel(const float* __restrict__ Whh_e, const float* __restrict__ bhh_e) {
    float* wst = esm;                // [256][193]
    float* hb  = esm + 49408;       // [2][256]
    float* ap  = esm + 49920;       // [192]
    const int tid = threadIdx.x;
    const int b = blockIdx.x >> 2;
    uint32_t rank;
    asm("mov.u32 %0, %%cluster_ctarank;" : "=r"(rank));

    for (int e = tid; e < 192 * 256; e += 256) {
        int row = e >> 8, k = e & 255;
        int g = row >> 6, jj = row & 63;
        wst[k * 193 + row] = Whh_e[(size_t)(g * 256 + rank * 64 + jj) * 256 + k];
    }
    hb[tid] = 0.f;
    hb[256 + tid] = 0.f;
    float bh = 0.f;
    if (tid < 192) {
        int g = tid >> 6, jj = tid & 63;
        bh = bhh_e[g * 256 + rank * 64 + jj];
    }
    __syncthreads();
    CLUSTER_SYNC();

    for (int l = 0; l < LE; ++l) {
        const float* hc = hb + (l & 1) * 256;
        if (tid < 192) {
            float a0 = 0.f, a1 = 0.f, a2 = 0.f, a3 = 0.f;
#pragma unroll 8
            for (int k = 0; k < 256; k += 4) {
                float4 hv = *(const float4*)&hc[k];
                a0 += wst[k * 193 + tid] * hv.x;
                a1 += wst[(k + 1) * 193 + tid] * hv.y;
                a2 += wst[(k + 2) * 193 + tid] * hv.z;
                a3 += wst[(k + 3) * 193 + tid] * hv.w;
            }
            ap[tid] = a0 + a1 + a2 + a3 + bh;
        }
        __syncthreads();
        if (tid < 64) {
            int j = rank * 64 + tid;
            const float* xp = g_xpe + (l * BB + b) * K3H;
            float r = sigf(xp[j] + ap[tid]);
            float z = sigf(xp[HH + j] + ap[64 + tid]);
            float n = tfast(xp[2 * HH + j] + r * ap[128 + tid]);
            float hn = n + z * (hc[j] - n);
            float* dst = hb + ((l + 1) & 1) * 256 + j;
            *dst = hn;
            uint32_t la = s2u(dst);
#pragma unroll
            for (int pr = 0; pr < 4; ++pr)
                if (pr != (int)rank) st_cl_f32(mapa_u32(la, (uint32_t)pr), hn);
        }
        CLUSTER_SYNC();
    }
    if (rank == 0) g_hT[b * HH + tid] = hb[(LE & 1) * 256 + tid];
}

__global__ void muz_kernel(const float* __restrict__ Wmu, const float* __restrict__ bmu,
                           const float* __restrict__ Wstd, const float* __restrict__ bstd,
                           const float* __restrict__ eps, float* __restrict__ out) {
    __shared__ float hs[HH];
    int b = blockIdx.x, j = threadIdx.x;
    hs[j] = g_hT[b * HH + j];
    __syncthreads();
    float am = bmu[j], as = bstd[j];
    const float* wm = Wmu + j * HH;
    const float* ws = Wstd + j * HH;
#pragma unroll 8
    for (int h = 0; h < HH; h += 4) {
        float4 hv = *(const float4*)&hs[h];
        float4 m4 = *(const float4*)(wm + h);
        float4 s4 = *(const float4*)(ws + h);
        am += m4.x * hv.x + m4.y * hv.y + m4.z * hv.z + m4.w * hv.w;
        as += s4.x * hv.x + s4.y * hv.y + s4.z * hv.z + s4.w * hv.w;
    }
    out[MU_OFF + b * HH + j] = am;
    out[LV_OFF + b * HH + j] = as;
    g_z[b * HH + j] = am + expf(0.5f * as) * eps[b * HH + j];
}

// ---- decoder: cluster(2) j-split, fp16 2-term split (480 HMMA/warp/step) ------
extern __shared__ unsigned char smem[];

__global__ void __launch_bounds__(288, 1) __cluster_dims__(2, 1, 1) dec_kernel(
    const float* __restrict__ bih_d, const float* __restrict__ bhh_d,
    const float* __restrict__ Wlin, const float* __restrict__ blin,
    float* __restrict__ out) {
    const int tid = threadIdx.x;
    const int p = blockIdx.x >> 1, jhalf = blockIdx.x & 1;
    const int w = tid >> 5, lane = tid & 31;
    const int wc = w - 1;
    const int g = lane >> 2, tig = lane & 3;
    const int ct = tid - 32;
    const uint32_t sb = s2u(smem);
    const uint32_t peer_sb = mapa_u32(sb, (uint32_t)(jhalf ^ 1));

    if (tid == 0) {
#pragma unroll
        for (int s = 0; s < RING; ++s) {
            mbar_init(sb + FULL_OFF + s * 8, 1);
            mbar_init(sb + EMPTY_OFF + s * 8, 8);
        }
        mbar_init(sb + STEP_OFF, 16);
        asm volatile("fence.proxy.async.shared::cta;" ::: "memory");
    }

    const int jbase = jhalf * 128 + (wc >= 0 ? wc * 16 : 0);
    float bR[2], bZ[2], bNx[2], bNh[2], wl[2];
    float hreg[16];
    if (wc >= 0) {
#pragma unroll
        for (int rr = 0; rr < 2; ++rr) {
            int j = jbase + g + rr * 8;
            bR[rr]  = bih_d[p * K3H + j] + bhh_d[p * K3H + j];
            bZ[rr]  = bih_d[p * K3H + 256 + j] + bhh_d[p * K3H + 256 + j];
            bNx[rr] = bih_d[p * K3H + 512 + j];
            bNh[rr] = bhh_d[p * K3H + 512 + j];
            wl[rr]  = Wlin[p * HH + j];
        }
#pragma unroll
        for (int nt = 0; nt < 4; ++nt)
#pragma unroll
            for (int q = 0; q < 4; ++q) {
                int j = jbase + g + (q >> 1) * 8;
                int bcol = nt * 8 + 2 * tig + (q & 1);
                hreg[nt * 4 + q] = g_z[bcol * HH + j];
            }
        // v[0] h-region: thread j = ct covers ALL 256 j, 32 b (local only)
        {
            int j = ct;
            for (int b = 0; b < BB; ++b) {
                uint32_t ad = V_OFF + ((uint32_t)(j >> 1) * 40 + b) * 4 + (j & 1) * 2;
                *(uint16_t*)(smem + ad) = hbits(g_z[b * HH + j]);
            }
        }
        // v[0] x-region
        for (int q = 0; q < 4; ++q) {
            int wd = ct * 4 + q;
            int k2 = wd >> 5, col = wd & 31;
            uint32_t ad = V_OFF + ((uint32_t)(128 + k2) * 40 + col) * 4;
            *(uint32_t*)(smem + ad) = g_Xpk[wd];
        }
    }
    const float blin_p = blin[p];
    __syncthreads();
    CLUSTER_SYNC();

    const uint32_t laneoff = (uint32_t)((((lane >> 3) & 1) * 8 + (lane & 7)) * 32 +
                                        ((lane >> 4) & 1) * 16);
    const unsigned char* wsrc = g_Wpk + (size_t)blockIdx.x * NCH * CHUNK_BYTES;
    float* red = (float*)(smem + RED_OFF);

    for (int l = 0; l < LSTEPS; ++l) {
        if (w == 0) {
            if (lane == 0) {
                for (int c = 0; c < NCH; ++c) {
                    int n = l * NCH + c, s = n & 3;
                    mwait(sb + EMPTY_OFF + s * 8, (uint32_t)(((n >> 2) + 1) & 1));
                    mbar_expect(sb + FULL_OFF + s * 8, CHUNK_BYTES);
                    bulk_cp(sb + RING_OFF + s * CHUNK_BYTES,
                            wsrc + (size_t)c * CHUNK_BYTES, CHUNK_BYTES,
                            sb + FULL_OFF + s * 8);
                }
            }
            __syncthreads();
        } else {
            const uint32_t vc = V_OFF + (uint32_t)(l & 1) * VBUF;
            const uint32_t vn = V_OFF + (uint32_t)((l + 1) & 1) * VBUF;
            float accR[4][4], accZ[4][4], accNh[4][4], accNx[4][4];
#pragma unroll
            for (int nt = 0; nt < 4; ++nt)
#pragma unroll
                for (int q = 0; q < 4; ++q) {
                    accR[nt][q] = 0.f; accZ[nt][q] = 0.f;
                    accNh[nt][q] = 0.f; accNx[nt][q] = 0.f;
                }

#pragma unroll 1
            for (int c = 0; c < NCH; ++c) {
                int n = l * NCH + c, s = n & 3;
                mwait(sb + FULL_OFF + s * 8, (uint32_t)((n >> 2) & 1));

                uint32_t bh[2][4];
#pragma unroll
                for (int hf = 0; hf < 2; ++hf)
#pragma unroll
                    for (int nt = 0; nt < 4; ++nt) {
                        uint32_t wo = vc + ((uint32_t)(8 * c + hf * 4 + tig) * 40 +
                                            nt * 8 + g) * 4;
                        bh[hf][nt] = *(const uint32_t*)(smem + wo);
                    }

                uint32_t tb = sb + RING_OFF + s * CHUNK_BYTES + wc * 3072 + laneoff;
#pragma unroll
                for (int gate = 0; gate < 3; ++gate) {
                    uint32_t ahi[4], alo[4];
                    lm4(ahi, tb + gate * 1024);
                    lm4(alo, tb + gate * 1024 + 512);
                    float (*acc)[4] =
                        (gate == 0) ? accR :
                        (gate == 1) ? accZ :
                        (c < 16 ? accNh : accNx);
#pragma unroll
                    for (int nt = 0; nt < 4; ++nt) {
                        mma16816h(acc[nt], ahi, bh[0][nt], bh[1][nt]);
                        mma16816h(acc[nt], alo, bh[0][nt], bh[1][nt]);
                    }
                }
                if (lane == 0) mbar_arrive(sb + EMPTY_OFF + s * 8);
            }

            // -------- epilogue: gates, h update, v[nxt] local + peer --------
            float part[8];
#pragma unroll
            for (int q = 0; q < 8; ++q) part[q] = 0.f;
#pragma unroll
            for (int nt = 0; nt < 4; ++nt)
#pragma unroll
                for (int q = 0; q < 4; ++q) {
                    int rr = q >> 1, cc = q & 1;
                    float r = sigf(accR[nt][q] + bR[rr]);
                    float z = sigf(accZ[nt][q] + bZ[rr]);
                    float nn = tfast(accNx[nt][q] + bNx[rr] +
                                     r * (accNh[nt][q] + bNh[rr]));
                    float hn = nn + z * (hreg[nt * 4 + q] - nn);
                    hreg[nt * 4 + q] = hn;
                    int j = jbase + g + rr * 8;
                    int bcol = nt * 8 + 2 * tig + cc;
                    uint16_t hu = hbits(hn);
                    uint32_t ad = vn + ((uint32_t)(j >> 1) * 40 + bcol) * 4 + (j & 1) * 2;
                    *(uint16_t*)(smem + ad) = hu;
                    st_cl_b16(peer_sb + ad, hu);
                    part[nt * 2 + cc] += hn * wl[rr];
                }
            // x region for step l+1 (local only)
            if (l + 1 < LSTEPS) {
                const uint32_t* src = g_Xpk + (size_t)(l + 1) * 1024;
#pragma unroll
                for (int q = 0; q < 4; ++q) {
                    int wd = ct * 4 + q;
                    int k2 = wd >> 5, col = wd & 31;
                    uint32_t ad = vn + ((uint32_t)(128 + k2) * 40 + col) * 4;
                    *(uint32_t*)(smem + ad) = src[wd];
                }
            }
            // reduce Wlin partials over g (shfl offsets 16, 8, 4)
#pragma unroll
            for (int off = 16; off >= 4; off >>= 1)
#pragma unroll
                for (int q = 0; q < 8; ++q)
                    part[q] += __shfl_down_sync(0xffffffffu, part[q], off);
            if (lane < 4) {
#pragma unroll
                for (int nt = 0; nt < 4; ++nt)
#pragma unroll
                    for (int cc = 0; cc < 2; ++cc)
                        red[wc * 32 + nt * 8 + 2 * lane + cc] = part[nt * 2 + cc];
            }
            __syncthreads();   // all local v/red writes CTA-visible

            float s0 = 0.f;
            if (w == 1) {
#pragma unroll
                for (int ww = 0; ww < 8; ++ww) s0 += red[ww * 32 + lane];
                st_cl_f32(peer_sb + PART_OFF + (uint32_t)(l & 1) * 128 + lane * 4, s0);
            }
            __syncwarp();      // PART stores HB lane0's release
            if (lane == 0) {
                mbar_arrive(sb + STEP_OFF);
                mbar_arrive_cluster_rel(peer_sb + STEP_OFF);
            }
            mwait_cl(sb + STEP_OFF, (uint32_t)(l & 1));
            if (w == 1 && jhalf == 0) {
                float ph = *(const float*)(smem + PART_OFF + (uint32_t)(l & 1) * 128 +
                                           lane * 4);
                out[(p * BB + lane) * LSTEPS + l] = s0 + ph + blin_p;
            }
        }
    }
    CLUSTER_SYNC();
}

// -----------------------------------------------------------------------------
extern "C" void kernel_launch(void* const* d_in, const int* in_sizes, int n_in,
                              void* d_out, int out_size) {
    const float* X     = (const float*)d_in[0];
    const float* eps   = (const float*)d_in[1];
    const float* Wih_e = (const float*)d_in[3];
    const float* Whh_e = (const float*)d_in[4];
    const float* bih_e = (const float*)d_in[5];
    const float* bhh_e = (const float*)d_in[6];
    const float* Wmu   = (const float*)d_in[7];
    const float* bmu   = (const float*)d_in[8];
    const float* Wstd  = (const float*)d_in[9];
    const float* bstd  = (const float*)d_in[10];
    const float* Wih_d = (const float*)d_in[11];
    const float* Whh_d = (const float*)d_in[12];
    const float* bih_d = (const float*)d_in[13];
    const float* bhh_d = (const float*)d_in[14];
    const float* Wlin  = (const float*)d_in[15];
    const float* blin  = (const float*)d_in[16];
    float* out = (float*)d_out;

    static int attr_set = 0;
    if (!attr_set) {
        cudaFuncSetAttribute(dec_kernel, cudaFuncAttributeMaxDynamicSharedMemorySize,
                             SMEM_TOTAL);
        cudaFuncSetAttribute(enc_kernel, cudaFuncAttributeMaxDynamicSharedMemorySize,
                             ENC_SMEM);
        attr_set = 1;
    }

    packW_kernel<<<dim3(PP * 2, NCH), 256>>>(Whh_d, Wih_d);
    packX_kernel<<<LSTEPS, 256>>>(X);
    xpe_kernel<<<dim3(BB, LE), 256>>>(X, Wih_e, bih_e);
    enc_kernel<<<BB * 4, 256, ENC_SMEM>>>(Whh_e, bhh_e);
    muz_kernel<<<BB, 256>>>(Wmu, bmu, Wstd, bstd, eps, out);
    dec_kernel<<<2 * PP, 288, SMEM_TOTAL>>>(bih_d, bhh_d, Wlin, blin, out);
}

// round 17
// speedup vs baseline: 1.6099x; 1.0989x over previous
#include <cuda_runtime.h>
#include <cuda_fp16.h>
#include <cstdint>

#define PP   64
#define HH   256
#define BB   32
#define TT   128
#define LE   10
#define LSTEPS 118
#define K3H  768
#define NCH  20
#define RING 4
#define CHUNK_BYTES 16384   // [wc(8)][Rhi,Zhi,Nhi,Nlo] x 512B

#define PRED_ELEMS (PP * BB * LSTEPS)
#define MU_OFF     PRED_ELEMS
#define LV_OFF     (PRED_ELEMS + BB * HH)

// ---- dec smem offsets ------------------------------------------------------
#define FULL_OFF   0        // 4 x 8B
#define EMPTY_OFF  32       // 4 x 8B
#define STEP_OFF   64       // 8B, count 16 (8 local + 8 remote lane0s)
#define PART_OFF   128      // 2 buf x 32 floats
#define RED_OFF    384      // 8 x 32 floats
#define V_OFF      1536     // 2 x VBUF (single fp16 plane)
#define VBUF       25600    // 160 rows x 40 words x 4B
#define RING_OFF   52736    // 1536 + 2*25600
#define SMEM_TOTAL 118272   // RING_OFF + 4*16384
#define ENC_SMEM   200448

__device__ __align__(16) unsigned char g_Wpk[(size_t)PP * 2 * NCH * CHUNK_BYTES];
__device__ uint32_t g_Xpk[LSTEPS * 1024];   // [l][k2(32)*32 + b], fp16x2 words
__device__ float g_xpe[LE * BB * K3H];
__device__ float g_hT[BB * HH];
__device__ float g_z[BB * HH];

typedef unsigned long long ull;
__device__ __forceinline__ uint32_t s2u(const void* p) {
    uint32_t a;
    asm("{ .reg .u64 t; cvta.to.shared.u64 t, %1; cvt.u32.u64 %0, t; }" : "=r"(a) : "l"(p));
    return a;
}
__device__ __forceinline__ float sigf(float x) { return __fdividef(1.0f, 1.0f + __expf(-x)); }
__device__ __forceinline__ float tfast(float x) {
    float e = __expf(2.0f * x);
    return 1.0f - __fdividef(2.0f, e + 1.0f);
}
__device__ __forceinline__ void mbar_init(uint32_t mb, uint32_t cnt) {
    asm volatile("mbarrier.init.shared.b64 [%0], %1;" :: "r"(mb), "r"(cnt) : "memory");
}
__device__ __forceinline__ void mbar_arrive(uint32_t mb) {
    asm volatile("mbarrier.arrive.shared.b64 _, [%0];" :: "r"(mb) : "memory");
}
__device__ __forceinline__ void mbar_arrive_cluster_rel(uint32_t mb) {
    asm volatile("mbarrier.arrive.release.cluster.shared::cluster.b64 _, [%0];"
                 :: "r"(mb) : "memory");
}
__device__ __forceinline__ void mbar_expect(uint32_t mb, uint32_t bytes) {
    asm volatile("mbarrier.arrive.expect_tx.shared.b64 _, [%0], %1;"
                 :: "r"(mb), "r"(bytes) : "memory");
}
__device__ __forceinline__ void mwait(uint32_t mb, uint32_t par) {
    asm volatile(
        "{\n\t.reg .pred P;\n"
        "LW%=:\n\t"
        "mbarrier.try_wait.parity.acquire.cta.shared::cta.b64 P, [%0], %1, 0x989680;\n\t"
        "@!P bra LW%=;\n\t}"
        :: "r"(mb), "r"(par) : "memory");
}
__device__ __forceinline__ void mwait_cl(uint32_t mb, uint32_t par) {
    asm volatile(
        "{\n\t.reg .pred P;\n"
        "LW%=:\n\t"
        "mbarrier.try_wait.parity.acquire.cluster.shared::cta.b64 P, [%0], %1, 0x989680;\n\t"
        "@!P bra LW%=;\n\t}"
        :: "r"(mb), "r"(par) : "memory");
}
__device__ __forceinline__ void bulk_cp(uint32_t dst, const void* src, uint32_t bytes,
                                        uint32_t mb) {
    asm volatile(
        "cp.async.bulk.shared::cluster.global.mbarrier::complete_tx::bytes [%0], [%1], %2, [%3];"
        :: "r"(dst), "l"(src), "r"(bytes), "r"(mb) : "memory");
}
__device__ __forceinline__ void lm4(uint32_t* r, uint32_t addr) {
    asm volatile("ldmatrix.sync.aligned.m8n8.x4.shared.b16 {%0,%1,%2,%3}, [%4];"
                 : "=r"(r[0]), "=r"(r[1]), "=r"(r[2]), "=r"(r[3]) : "r"(addr));
}
__device__ __forceinline__ void mma16816h(float* c, const uint32_t* a,
                                          uint32_t b0, uint32_t b1) {
    asm volatile(
        "mma.sync.aligned.m16n8k16.row.col.f32.f16.f16.f32 "
        "{%0,%1,%2,%3}, {%4,%5,%6,%7}, {%8,%9}, {%0,%1,%2,%3};"
        : "+f"(c[0]), "+f"(c[1]), "+f"(c[2]), "+f"(c[3])
        : "r"(a[0]), "r"(a[1]), "r"(a[2]), "r"(a[3]), "r"(b0), "r"(b1));
}
__device__ __forceinline__ uint32_t packh2(float v0, float v1) {
    __half h0 = __float2half(v0), h1 = __float2half(v1);
    uint16_t u0 = *(uint16_t*)&h0, u1 = *(uint16_t*)&h1;
    return (uint32_t)u0 | ((uint32_t)u1 << 16);
}
__device__ __forceinline__ uint16_t hbits(float v) {
    __half h = __float2half(v);
    return *(uint16_t*)&h;
}
__device__ __forceinline__ uint32_t mapa_u32(uint32_t addr, uint32_t rank) {
    uint32_t r;
    asm("mapa.shared::cluster.u32 %0, %1, %2;" : "=r"(r) : "r"(addr), "r"(rank));
    return r;
}
__device__ __forceinline__ void st_cl_b16(uint32_t addr, uint16_t v) {
    asm volatile("st.shared::cluster.b16 [%0], %1;" :: "r"(addr), "h"(v) : "memory");
}
__device__ __forceinline__ void st_cl_f32(uint32_t addr, float v) {
    asm volatile("st.shared::cluster.f32 [%0], %1;" :: "r"(addr), "f"(v) : "memory");
}
#define CLUSTER_SYNC() do { \
    asm volatile("barrier.cluster.arrive.aligned;" ::: "memory"); \
    asm volatile("barrier.cluster.wait.aligned;" ::: "memory"); } while (0)

// ---- prepack weights: [wc(8)][tile(4): Rhi, Zhi, Nhi, Nlo] x 512B -------------
__global__ void packW_kernel(const float* __restrict__ Whh,
                             const float* __restrict__ Wih) {
    int bx = blockIdx.x, c = blockIdx.y;   // bx = p*2 + jhalf
    int p = bx >> 1, jhalf = bx & 1;
    unsigned char* img = g_Wpk + ((size_t)bx * NCH + c) * CHUNK_BYTES;
    // 8 wc x 3 gates x 16 rows x 16 cols = 6144 source elements
    for (int idx = threadIdx.x; idx < 6144; idx += 256) {
        int kk = idx & 15, t = idx >> 4;
        int r = t & 15, t2 = t >> 4;
        int g = t2 % 3, wc = t2 / 3;
        int j = jhalf * 128 + wc * 16 + r;
        int k = c * 16 + kk;
        float v = (c < 16)
            ? Whh[((size_t)p * K3H + g * 256 + j) * HH + k]
            : Wih[((size_t)p * K3H + g * 256 + j) * PP + (k - 256)];
        __half hi = __float2half(v);
        uint32_t inoff = (uint32_t)(r * 32 + kk * 2);
        if (g < 2) {
            // R (tile 0) / Z (tile 1): hi only
            *(__half*)(img + (uint32_t)(wc * 4 + g) * 512 + inoff) = hi;
        } else {
            // N: hi (tile 2) + lo (tile 3)
            __half lo = __float2half(v - __half2float(hi));
            *(__half*)(img + (uint32_t)(wc * 4 + 2) * 512 + inoff) = hi;
            *(__half*)(img + (uint32_t)(wc * 4 + 3) * 512 + inoff) = lo;
        }
    }
}

// ---- prepack x words: [l][k2*32 + b], fp16 pair {x[2k2], x[2k2+1]} ------------
__global__ void packX_kernel(const float* __restrict__ X) {
    int l = blockIdx.x;
    for (int e = threadIdx.x; e < 1024; e += 256) {
        int k2 = e >> 5, b = e & 31;
        float v0 = 0.f, v1 = 0.f;
        if (l != 0) {
            v0 = X[(size_t)b * TT * PP + (l + 9) * PP + 2 * k2];
            v1 = X[(size_t)b * TT * PP + (l + 9) * PP + 2 * k2 + 1];
        }
        g_Xpk[l * 1024 + e] = packh2(v0, v1);
    }
}

__global__ void xpe_kernel(const float* __restrict__ X,
                           const float* __restrict__ Wih_e,
                           const float* __restrict__ bih_e) {
    __shared__ float xr[PP];
    int b = blockIdx.x, l = blockIdx.y, tid = threadIdx.x;
    if (tid < PP) xr[tid] = X[b * (TT * PP) + l * PP + tid];
    __syncthreads();
#pragma unroll
    for (int g = 0; g < 3; ++g) {
        int k = g * HH + tid;
        float a = bih_e[k];
        const float* w = Wih_e + k * PP;
#pragma unroll
        for (int i = 0; i < PP; i += 4) {
            float4 wv = *(const float4*)(w + i);
            a += wv.x * xr[i] + wv.y * xr[i + 1] + wv.z * xr[i + 2] + wv.w * xr[i + 3];
        }
        g_xpe[(l * BB + b) * K3H + k] = a;
    }
}

// ---- encoder GRU: cluster(4) per batch element, smem-resident weights --------
extern __shared__ float esm[];
__global__ void __launch_bounds__(256, 1) __cluster_dims__(4, 1, 1)
enc_kernel(const float* __restrict__ Whh_e, const float* __restrict__ bhh_e) {
    float* wst = esm;                // [256][193]
    float* hb  = esm + 49408;       // [2][256]
    float* ap  = esm + 49920;       // [192]
    const int tid = threadIdx.x;
    const int b = blockIdx.x >> 2;
    uint32_t rank;
    asm("mov.u32 %0, %%cluster_ctarank;" : "=r"(rank));

    for (int e = tid; e < 192 * 256; e += 256) {
        int row = e >> 8, k = e & 255;
        int g = row >> 6, jj = row & 63;
        wst[k * 193 + row] = Whh_e[(size_t)(g * 256 + rank * 64 + jj) * 256 + k];
    }
    hb[tid] = 0.f;
    hb[256 + tid] = 0.f;
    float bh = 0.f;
    if (tid < 192) {
        int g = tid >> 6, jj = tid & 63;
        bh = bhh_e[g * 256 + rank * 64 + jj];
    }
    __syncthreads();
    CLUSTER_SYNC();

    for (int l = 0; l < LE; ++l) {
        const float* hc = hb + (l & 1) * 256;
        if (tid < 192) {
            float a0 = 0.f, a1 = 0.f, a2 = 0.f, a3 = 0.f;
#pragma unroll 8
            for (int k = 0; k < 256; k += 4) {
                float4 hv = *(const float4*)&hc[k];
                a0 += wst[k * 193 + tid] * hv.x;
                a1 += wst[(k + 1) * 193 + tid] * hv.y;
                a2 += wst[(k + 2) * 193 + tid] * hv.z;
                a3 += wst[(k + 3) * 193 + tid] * hv.w;
            }
            ap[tid] = a0 + a1 + a2 + a3 + bh;
        }
        __syncthreads();
        if (tid < 64) {
            int j = rank * 64 + tid;
            const float* xp = g_xpe + (l * BB + b) * K3H;
            float r = sigf(xp[j] + ap[tid]);
            float z = sigf(xp[HH + j] + ap[64 + tid]);
            float n = tfast(xp[2 * HH + j] + r * ap[128 + tid]);
            float hn = n + z * (hc[j] - n);
            float* dst = hb + ((l + 1) & 1) * 256 + j;
            *dst = hn;
            uint32_t la = s2u(dst);
#pragma unroll
            for (int pr = 0; pr < 4; ++pr)
                if (pr != (int)rank) st_cl_f32(mapa_u32(la, (uint32_t)pr), hn);
        }
        CLUSTER_SYNC();
    }
    if (rank == 0) g_hT[b * HH + tid] = hb[(LE & 1) * 256 + tid];
}

__global__ void muz_kernel(const float* __restrict__ Wmu, const float* __restrict__ bmu,
                           const float* __restrict__ Wstd, const float* __restrict__ bstd,
                           const float* __restrict__ eps, float* __restrict__ out) {
    __shared__ float hs[HH];
    int b = blockIdx.x, j = threadIdx.x;
    hs[j] = g_hT[b * HH + j];
    __syncthreads();
    float am = bmu[j], as = bstd[j];
    const float* wm = Wmu + j * HH;
    const float* ws = Wstd + j * HH;
#pragma unroll 8
    for (int h = 0; h < HH; h += 4) {
        float4 hv = *(const float4*)&hs[h];
        float4 m4 = *(const float4*)(wm + h);
        float4 s4 = *(const float4*)(ws + h);
        am += m4.x * hv.x + m4.y * hv.y + m4.z * hv.z + m4.w * hv.w;
        as += s4.x * hv.x + s4.y * hv.y + s4.z * hv.z + s4.w * hv.w;
    }
    out[MU_OFF + b * HH + j] = am;
    out[LV_OFF + b * HH + j] = as;
    g_z[b * HH + j] = am + expf(0.5f * as) * eps[b * HH + j];
}

// ---- decoder: cluster(2) j-split, fp16; R/Z 1-term, N 2-term (320 HMMA/warp) --
extern __shared__ unsigned char smem[];

__global__ void __launch_bounds__(288, 1) __cluster_dims__(2, 1, 1) dec_kernel(
    const float* __restrict__ bih_d, const float* __restrict__ bhh_d,
    const float* __restrict__ Wlin, const float* __restrict__ blin,
    float* __restrict__ out) {
    const int tid = threadIdx.x;
    const int p = blockIdx.x >> 1, jhalf = blockIdx.x & 1;
    const int w = tid >> 5, lane = tid & 31;
    const int wc = w - 1;
    const int g = lane >> 2, tig = lane & 3;
    const int ct = tid - 32;
    const uint32_t sb = s2u(smem);
    const uint32_t peer_sb = mapa_u32(sb, (uint32_t)(jhalf ^ 1));

    if (tid == 0) {
#pragma unroll
        for (int s = 0; s < RING; ++s) {
            mbar_init(sb + FULL_OFF + s * 8, 1);
            mbar_init(sb + EMPTY_OFF + s * 8, 8);
        }
        mbar_init(sb + STEP_OFF, 16);
        asm volatile("fence.proxy.async.shared::cta;" ::: "memory");
    }

    const int jbase = jhalf * 128 + (wc >= 0 ? wc * 16 : 0);
    float bR[2], bZ[2], bNx[2], bNh[2], wl[2];
    float hreg[16];
    if (wc >= 0) {
#pragma unroll
        for (int rr = 0; rr < 2; ++rr) {
            int j = jbase + g + rr * 8;
            bR[rr]  = bih_d[p * K3H + j] + bhh_d[p * K3H + j];
            bZ[rr]  = bih_d[p * K3H + 256 + j] + bhh_d[p * K3H + 256 + j];
            bNx[rr] = bih_d[p * K3H + 512 + j];
            bNh[rr] = bhh_d[p * K3H + 512 + j];
            wl[rr]  = Wlin[p * HH + j];
        }
#pragma unroll
        for (int nt = 0; nt < 4; ++nt)
#pragma unroll
            for (int q = 0; q < 4; ++q) {
                int j = jbase + g + (q >> 1) * 8;
                int bcol = nt * 8 + 2 * tig + (q & 1);
                hreg[nt * 4 + q] = g_z[bcol * HH + j];
            }
        // v[0] h-region
        {
            int j = ct;
            for (int b = 0; b < BB; ++b) {
                uint32_t ad = V_OFF + ((uint32_t)(j >> 1) * 40 + b) * 4 + (j & 1) * 2;
                *(uint16_t*)(smem + ad) = hbits(g_z[b * HH + j]);
            }
        }
        // v[0] x-region
        for (int q = 0; q < 4; ++q) {
            int wd = ct * 4 + q;
            int k2 = wd >> 5, col = wd & 31;
            uint32_t ad = V_OFF + ((uint32_t)(128 + k2) * 40 + col) * 4;
            *(uint32_t*)(smem + ad) = g_Xpk[wd];
        }
    }
    const float blin_p = blin[p];
    __syncthreads();
    CLUSTER_SYNC();

    const uint32_t laneoff = (uint32_t)((((lane >> 3) & 1) * 8 + (lane & 7)) * 32 +
                                        ((lane >> 4) & 1) * 16);
    const unsigned char* wsrc = g_Wpk + (size_t)blockIdx.x * NCH * CHUNK_BYTES;
    float* red = (float*)(smem + RED_OFF);

    for (int l = 0; l < LSTEPS; ++l) {
        if (w == 0) {
            if (lane == 0) {
                for (int c = 0; c < NCH; ++c) {
                    int n = l * NCH + c, s = n & 3;
                    mwait(sb + EMPTY_OFF + s * 8, (uint32_t)(((n >> 2) + 1) & 1));
                    mbar_expect(sb + FULL_OFF + s * 8, CHUNK_BYTES);
                    bulk_cp(sb + RING_OFF + s * CHUNK_BYTES,
                            wsrc + (size_t)c * CHUNK_BYTES, CHUNK_BYTES,
                            sb + FULL_OFF + s * 8);
                }
            }
            __syncthreads();
        } else {
            const uint32_t vc = V_OFF + (uint32_t)(l & 1) * VBUF;
            const uint32_t vn = V_OFF + (uint32_t)((l + 1) & 1) * VBUF;
            float accR[4][4], accZ[4][4], accNh[4][4], accNx[4][4];
#pragma unroll
            for (int nt = 0; nt < 4; ++nt)
#pragma unroll
                for (int q = 0; q < 4; ++q) {
                    accR[nt][q] = 0.f; accZ[nt][q] = 0.f;
                    accNh[nt][q] = 0.f; accNx[nt][q] = 0.f;
                }

#pragma unroll 1
            for (int c = 0; c < NCH; ++c) {
                int n = l * NCH + c, s = n & 3;
                mwait(sb + FULL_OFF + s * 8, (uint32_t)((n >> 2) & 1));

                uint32_t bh[2][4];
#pragma unroll
                for (int hf = 0; hf < 2; ++hf)
#pragma unroll
                    for (int nt = 0; nt < 4; ++nt) {
                        uint32_t wo = vc + ((uint32_t)(8 * c + hf * 4 + tig) * 40 +
                                            nt * 8 + g) * 4;
                        bh[hf][nt] = *(const uint32_t*)(smem + wo);
                    }

                uint32_t tb = sb + RING_OFF + s * CHUNK_BYTES + wc * 2048 + laneoff;
                uint32_t aR[4], aZ[4], aNh4[4], aNl[4];
                lm4(aR,   tb);
                lm4(aZ,   tb + 512);
                lm4(aNh4, tb + 1024);
                lm4(aNl,  tb + 1536);
                float (*accN)[4] = (c < 16) ? accNh : accNx;
#pragma unroll
                for (int nt = 0; nt < 4; ++nt) {
                    mma16816h(accR[nt], aR,   bh[0][nt], bh[1][nt]);
                    mma16816h(accZ[nt], aZ,   bh[0][nt], bh[1][nt]);
                    mma16816h(accN[nt], aNh4, bh[0][nt], bh[1][nt]);
                    mma16816h(accN[nt], aNl,  bh[0][nt], bh[1][nt]);
                }
                if (lane == 0) mbar_arrive(sb + EMPTY_OFF + s * 8);
            }

            // -------- epilogue: gates, h update, v[nxt] local + peer --------
            float part[8];
#pragma unroll
            for (int q = 0; q < 8; ++q) part[q] = 0.f;
#pragma unroll
            for (int nt = 0; nt < 4; ++nt)
#pragma unroll
                for (int q = 0; q < 4; ++q) {
                    int rr = q >> 1, cc = q & 1;
                    float r = sigf(accR[nt][q] + bR[rr]);
                    float z = sigf(accZ[nt][q] + bZ[rr]);
                    float nn = tfast(accNx[nt][q] + bNx[rr] +
                                     r * (accNh[nt][q] + bNh[rr]));
                    float hn = nn + z * (hreg[nt * 4 + q] - nn);
                    hreg[nt * 4 + q] = hn;
                    int j = jbase + g + rr * 8;
                    int bcol = nt * 8 + 2 * tig + cc;
                    uint16_t hu = hbits(hn);
                    uint32_t ad = vn + ((uint32_t)(j >> 1) * 40 + bcol) * 4 + (j & 1) * 2;
                    *(uint16_t*)(smem + ad) = hu;
                    st_cl_b16(peer_sb + ad, hu);
                    part[nt * 2 + cc] += hn * wl[rr];
                }
            // x region for step l+1 (local only)
            if (l + 1 < LSTEPS) {
                const uint32_t* src = g_Xpk + (size_t)(l + 1) * 1024;
#pragma unroll
                for (int q = 0; q < 4; ++q) {
                    int wd = ct * 4 + q;
                    int k2 = wd >> 5, col = wd & 31;
                    uint32_t ad = vn + ((uint32_t)(128 + k2) * 40 + col) * 4;
                    *(uint32_t*)(smem + ad) = src[wd];
                }
            }
            // reduce Wlin partials over g (shfl offsets 16, 8, 4)
#pragma unroll
            for (int off = 16; off >= 4; off >>= 1)
#pragma unroll
                for (int q = 0; q < 8; ++q)
                    part[q] += __shfl_down_sync(0xffffffffu, part[q], off);
            if (lane < 4) {
#pragma unroll
                for (int nt = 0; nt < 4; ++nt)
#pragma unroll
                    for (int cc = 0; cc < 2; ++cc)
                        red[wc * 32 + nt * 8 + 2 * lane + cc] = part[nt * 2 + cc];
            }
            __syncthreads();   // all local v/red writes CTA-visible

            float s0 = 0.f;
            if (w == 1) {
#pragma unroll
                for (int ww = 0; ww < 8; ++ww) s0 += red[ww * 32 + lane];
                st_cl_f32(peer_sb + PART_OFF + (uint32_t)(l & 1) * 128 + lane * 4, s0);
            }
            __syncwarp();      // PART stores HB lane0's release
            if (lane == 0) {
                mbar_arrive(sb + STEP_OFF);
                mbar_arrive_cluster_rel(peer_sb + STEP_OFF);
            }
            mwait_cl(sb + STEP_OFF, (uint32_t)(l & 1));
            if (w == 1 && jhalf == 0) {
                float ph = *(const float*)(smem + PART_OFF + (uint32_t)(l & 1) * 128 +
                                           lane * 4);
                out[(p * BB + lane) * LSTEPS + l] = s0 + ph + blin_p;
            }
        }
    }
    CLUSTER_SYNC();
}

// -----------------------------------------------------------------------------
extern "C" void kernel_launch(void* const* d_in, const int* in_sizes, int n_in,
                              void* d_out, int out_size) {
    const float* X     = (const float*)d_in[0];
    const float* eps   = (const float*)d_in[1];
    const float* Wih_e = (const float*)d_in[3];
    const float* Whh_e = (const float*)d_in[4];
    const float* bih_e = (const float*)d_in[5];
    const float* bhh_e = (const float*)d_in[6];
    const float* Wmu   = (const float*)d_in[7];
    const float* bmu   = (const float*)d_in[8];
    const float* Wstd  = (const float*)d_in[9];
    const float* bstd  = (const float*)d_in[10];
    const float* Wih_d = (const float*)d_in[11];
    const float* Whh_d = (const float*)d_in[12];
    const float* bih_d = (const float*)d_in[13];
    const float* bhh_d = (const float*)d_in[14];
    const float* Wlin  = (const float*)d_in[15];
    const float* blin  = (const float*)d_in[16];
    float* out = (float*)d_out;

    static int attr_set = 0;
    if (!attr_set) {
        cudaFuncSetAttribute(dec_kernel, cudaFuncAttributeMaxDynamicSharedMemorySize,
                             SMEM_TOTAL);
        cudaFuncSetAttribute(enc_kernel, cudaFuncAttributeMaxDynamicSharedMemorySize,
                             ENC_SMEM);
        attr_set = 1;
    }

    packW_kernel<<<dim3(PP * 2, NCH), 256>>>(Whh_d, Wih_d);
    packX_kernel<<<LSTEPS, 256>>>(X);
    xpe_kernel<<<dim3(BB, LE), 256>>>(X, Wih_e, bih_e);
    enc_kernel<<<BB * 4, 256, ENC_SMEM>>>(Whh_e, bhh_e);
    muz_kernel<<<BB, 256>>>(Wmu, bmu, Wstd, bstd, eps, out);
    dec_kernel<<<2 * PP, 288, SMEM_TOTAL>>>(bih_d, bhh_d, Wlin, blin, out);
}